// round 1
// baseline (speedup 1.0000x reference)
#include <cuda_runtime.h>
#include <cuda_bf16.h>
#include <cstdint>
#include <cstddef>

// Problem constants
#define BB 2
#define TT 2048
#define CC 2048
#define HH 16
#define DH 128
#define M_ROWS (BB*TT)          // 4096
#define QKV_N  (3*CC)           // 6144

// Scratch (allocation-free rule: __device__ globals)
__device__ float g_qkv[(size_t)M_ROWS * QKV_N];   // 96 MB
__device__ float g_y  [(size_t)M_ROWS * CC];      // 32 MB

// ---------------------------------------------------------------------------
// SGEMM with bias: C[M,N] = A[M,K] @ B[K,N] + bias[N]
// BM=BN=128, BK=8, 256 threads, 8x8 per thread. All dims divisible.
// ---------------------------------------------------------------------------
__global__ __launch_bounds__(256)
void sgemm_bias_kernel(const float* __restrict__ A, const float* __restrict__ B,
                       const float* __restrict__ bias, float* __restrict__ C,
                       int M, int N, int K) {
    __shared__ float As[8][128];
    __shared__ float Bs[8][128];

    const int tid = threadIdx.x;
    const int tx = tid & 15;
    const int ty = tid >> 4;
    const int row0 = blockIdx.y * 128;
    const int col0 = blockIdx.x * 128;

    const int ar = tid >> 1;          // 0..127
    const int ac = (tid & 1) * 4;     // 0 or 4
    const int br = tid >> 5;          // 0..7
    const int bc = (tid & 31) * 4;    // 0..124

    const float* Aptr = A + (size_t)row0 * K;
    const float* Bptr = B + col0;

    float c[8][8];
#pragma unroll
    for (int i = 0; i < 8; i++)
#pragma unroll
        for (int j = 0; j < 8; j++) c[i][j] = 0.0f;

    for (int k0 = 0; k0 < K; k0 += 8) {
        float4 av = *(const float4*)(Aptr + (size_t)ar * K + k0 + ac);
        float4 bv = *(const float4*)(Bptr + (size_t)(k0 + br) * N + bc);
        __syncthreads();
        As[ac + 0][ar] = av.x;
        As[ac + 1][ar] = av.y;
        As[ac + 2][ar] = av.z;
        As[ac + 3][ar] = av.w;
        *(float4*)&Bs[br][bc] = bv;
        __syncthreads();
#pragma unroll
        for (int k = 0; k < 8; k++) {
            float a[8], bf[8];
            *(float4*)&a[0]  = *(float4*)&As[k][ty * 8];
            *(float4*)&a[4]  = *(float4*)&As[k][ty * 8 + 4];
            *(float4*)&bf[0] = *(float4*)&Bs[k][tx * 8];
            *(float4*)&bf[4] = *(float4*)&Bs[k][tx * 8 + 4];
#pragma unroll
            for (int i = 0; i < 8; i++)
#pragma unroll
                for (int j = 0; j < 8; j++)
                    c[i][j] = fmaf(a[i], bf[j], c[i][j]);
        }
    }

#pragma unroll
    for (int i = 0; i < 8; i++) {
        size_t r = (size_t)(row0 + ty * 8 + i);
#pragma unroll
        for (int j = 0; j < 8; j += 4) {
            int cc = col0 + tx * 8 + j;
            float4 bvv = *(const float4*)(bias + cc);
            float4 o;
            o.x = c[i][j + 0] + bvv.x;
            o.y = c[i][j + 1] + bvv.y;
            o.z = c[i][j + 2] + bvv.z;
            o.w = c[i][j + 3] + bvv.w;
            *(float4*)(C + r * N + cc) = o;
        }
    }
}

// ---------------------------------------------------------------------------
// Flash attention (fp32, causal). Grid: (B*H, T/64). 256 threads.
// Q tile 64x128 in smem; per KV tile 64: K transposed (pad 68), V natural,
// P staged in smem (pad 68). Thread (tx,ty) 16x16 grid:
//   S: 4 rows x 4 cols; PV/out: 4 rows x 8 dims.
// ---------------------------------------------------------------------------
#define ATTN_SMEM_FLOATS (64*128 + 128*68 + 64*128 + 64*68)
#define ATTN_SMEM_BYTES  (ATTN_SMEM_FLOATS * 4)

__global__ __launch_bounds__(256)
void attn_kernel(const float* __restrict__ qkv, float* __restrict__ y) {
    extern __shared__ float sm[];
    float* Qs = sm;                    // 64*128
    float* Kt = Qs + 64 * 128;         // 128*68 (transposed, padded)
    float* Vs = Kt + 128 * 68;         // 64*128
    float* Ps = Vs + 64 * 128;         // 64*68

    const int tid = threadIdx.x;
    const int tx = tid & 15;
    const int ty = tid >> 4;
    const int bh = blockIdx.x;
    const int qt = blockIdx.y;
    const int b = bh >> 4;
    const int h = bh & 15;
    const int q0 = qt * 64;

    const float SCALE = 0.08838834764831845f;   // 1/sqrt(128)
    const size_t RS = (size_t)QKV_N;            // 6144

    const float* qbase = qkv + (size_t)b * TT * RS + (size_t)h * DH;
    const float* kbase = qbase + CC;
    const float* vbase = qbase + 2 * CC;

    // Load Q tile (64 rows x 128)
    for (int i = tid; i < 64 * 32; i += 256) {
        int r = i >> 5, dv = i & 31;
        *(float4*)&Qs[r * 128 + dv * 4] =
            *(const float4*)(qbase + (size_t)(q0 + r) * RS + dv * 4);
    }

    float m_prev[4], l_acc[4], acc[4][8];
#pragma unroll
    for (int i = 0; i < 4; i++) {
        m_prev[i] = -1e30f;
        l_acc[i] = 0.0f;
#pragma unroll
        for (int j = 0; j < 8; j++) acc[i][j] = 0.0f;
    }

    const int ntiles = qt + 1;   // causal: only tiles at/below diagonal
    for (int kt = 0; kt < ntiles; ++kt) {
        const int k0 = kt * 64;
        __syncthreads();   // prior-iter smem reads done (also fences Q on iter 0)

        // Load K transposed + V natural
        for (int i = tid; i < 64 * 32; i += 256) {
            int r = i >> 5, dv = i & 31;
            float4 kv = *(const float4*)(kbase + (size_t)(k0 + r) * RS + dv * 4);
            int dbase = dv * 4;
            Kt[(dbase + 0) * 68 + r] = kv.x;
            Kt[(dbase + 1) * 68 + r] = kv.y;
            Kt[(dbase + 2) * 68 + r] = kv.z;
            Kt[(dbase + 3) * 68 + r] = kv.w;
            *(float4*)&Vs[r * 128 + dbase] =
                *(const float4*)(vbase + (size_t)(k0 + r) * RS + dbase);
        }
        __syncthreads();

        // ---- S = Q K^T (4x4 per thread) ----
        float s[4][4];
#pragma unroll
        for (int i = 0; i < 4; i++)
#pragma unroll
            for (int j = 0; j < 4; j++) s[i][j] = 0.0f;

        for (int d = 0; d < 128; d += 4) {
            float4 a0 = *(float4*)&Qs[(ty * 4 + 0) * 128 + d];
            float4 a1 = *(float4*)&Qs[(ty * 4 + 1) * 128 + d];
            float4 a2 = *(float4*)&Qs[(ty * 4 + 2) * 128 + d];
            float4 a3 = *(float4*)&Qs[(ty * 4 + 3) * 128 + d];
            float4 b0 = *(float4*)&Kt[(d + 0) * 68 + tx * 4];
            float4 b1 = *(float4*)&Kt[(d + 1) * 68 + tx * 4];
            float4 b2 = *(float4*)&Kt[(d + 2) * 68 + tx * 4];
            float4 b3 = *(float4*)&Kt[(d + 3) * 68 + tx * 4];
#define SROW(i, av)                                             \
            s[i][0] = fmaf(av.x, b0.x, s[i][0]);                \
            s[i][1] = fmaf(av.x, b0.y, s[i][1]);                \
            s[i][2] = fmaf(av.x, b0.z, s[i][2]);                \
            s[i][3] = fmaf(av.x, b0.w, s[i][3]);                \
            s[i][0] = fmaf(av.y, b1.x, s[i][0]);                \
            s[i][1] = fmaf(av.y, b1.y, s[i][1]);                \
            s[i][2] = fmaf(av.y, b1.z, s[i][2]);                \
            s[i][3] = fmaf(av.y, b1.w, s[i][3]);                \
            s[i][0] = fmaf(av.z, b2.x, s[i][0]);                \
            s[i][1] = fmaf(av.z, b2.y, s[i][1]);                \
            s[i][2] = fmaf(av.z, b2.z, s[i][2]);                \
            s[i][3] = fmaf(av.z, b2.w, s[i][3]);                \
            s[i][0] = fmaf(av.w, b3.x, s[i][0]);                \
            s[i][1] = fmaf(av.w, b3.y, s[i][1]);                \
            s[i][2] = fmaf(av.w, b3.z, s[i][2]);                \
            s[i][3] = fmaf(av.w, b3.w, s[i][3]);
            SROW(0, a0) SROW(1, a1) SROW(2, a2) SROW(3, a3)
#undef SROW
        }

        // ---- mask + scale + row max over 64 cols (16-lane shfl) ----
        float mt[4];
#pragma unroll
        for (int i = 0; i < 4; i++) {
            int gr = q0 + ty * 4 + i;
            float mx = -1e30f;
#pragma unroll
            for (int j = 0; j < 4; j++) {
                int gc = k0 + tx * 4 + j;
                float sv = s[i][j] * SCALE;
                sv = (gc > gr) ? -1e30f : sv;
                s[i][j] = sv;
                mx = fmaxf(mx, sv);
            }
            mt[i] = mx;
        }
#pragma unroll
        for (int off = 8; off >= 1; off >>= 1) {
#pragma unroll
            for (int i = 0; i < 4; i++)
                mt[i] = fmaxf(mt[i], __shfl_xor_sync(0xffffffffu, mt[i], off));
        }

        // ---- online softmax update + write P ----
#pragma unroll
        for (int i = 0; i < 4; i++) {
            float mn = fmaxf(m_prev[i], mt[i]);
            float sc = __expf(m_prev[i] - mn);
            float ls = 0.0f;
#pragma unroll
            for (int j = 0; j < 4; j++) {
                float p = __expf(s[i][j] - mn);
                s[i][j] = p;
                ls += p;
            }
#pragma unroll
            for (int off = 8; off >= 1; off >>= 1)
                ls += __shfl_xor_sync(0xffffffffu, ls, off);
            l_acc[i] = l_acc[i] * sc + ls;
            m_prev[i] = mn;
#pragma unroll
            for (int j = 0; j < 8; j++) acc[i][j] *= sc;
            float4 pv = make_float4(s[i][0], s[i][1], s[i][2], s[i][3]);
            *(float4*)&Ps[(ty * 4 + i) * 68 + tx * 4] = pv;
        }
        __syncwarp();   // P rows are produced/consumed within the same 16-lane group

        // ---- acc += P @ V (4 rows x 8 dims per thread) ----
        for (int k = 0; k < 64; ++k) {
            float4 v0 = *(float4*)&Vs[k * 128 + tx * 8];
            float4 v1 = *(float4*)&Vs[k * 128 + tx * 8 + 4];
#pragma unroll
            for (int i = 0; i < 4; i++) {
                float p = Ps[(ty * 4 + i) * 68 + k];
                acc[i][0] = fmaf(p, v0.x, acc[i][0]);
                acc[i][1] = fmaf(p, v0.y, acc[i][1]);
                acc[i][2] = fmaf(p, v0.z, acc[i][2]);
                acc[i][3] = fmaf(p, v0.w, acc[i][3]);
                acc[i][4] = fmaf(p, v1.x, acc[i][4]);
                acc[i][5] = fmaf(p, v1.y, acc[i][5]);
                acc[i][6] = fmaf(p, v1.z, acc[i][6]);
                acc[i][7] = fmaf(p, v1.w, acc[i][7]);
            }
        }
        __syncwarp();   // finish reading Ps before next iter overwrites it
    }

    // ---- normalize and write y[b, q, h*Dh + d] ----
#pragma unroll
    for (int i = 0; i < 4; i++) {
        float inv = 1.0f / l_acc[i];
        size_t orow = (size_t)(b * TT + q0 + ty * 4 + i) * CC + h * DH + tx * 8;
        float4 o0, o1;
        o0.x = acc[i][0] * inv; o0.y = acc[i][1] * inv;
        o0.z = acc[i][2] * inv; o0.w = acc[i][3] * inv;
        o1.x = acc[i][4] * inv; o1.y = acc[i][5] * inv;
        o1.z = acc[i][6] * inv; o1.w = acc[i][7] * inv;
        *(float4*)(y + orow) = o0;
        *(float4*)(y + orow + 4) = o1;
    }
}

// ---------------------------------------------------------------------------
// cache[bt, 0:2C] = qkv[bt, C:3C]   (float4 copy)
// ---------------------------------------------------------------------------
__global__ __launch_bounds__(256)
void cache_copy_kernel(const float* __restrict__ qkv, float* __restrict__ cache) {
    int idx = blockIdx.x * blockDim.x + threadIdx.x;   // f4 index, total 4096*1024
    int bt = idx >> 10;
    int c4 = idx & 1023;
    const float4* src = (const float4*)qkv + (size_t)bt * 1536 + 512 + c4;
    ((float4*)cache)[idx] = *src;
}

// ---------------------------------------------------------------------------
extern "C" void kernel_launch(void* const* d_in, const int* in_sizes, int n_in,
                              void* d_out, int out_size) {
    (void)in_sizes; (void)n_in; (void)out_size;
    const float* x      = (const float*)d_in[0];
    // d_in[1] = attention_mask (always exact causal -1e9; implemented analytically)
    const float* W_attn = (const float*)d_in[2];
    const float* b_attn = (const float*)d_in[3];
    const float* W_proj = (const float*)d_in[4];
    const float* b_proj = (const float*)d_in[5];

    float* out   = (float*)d_out;
    float* y_out = out;                               // [B,T,C]
    float* cache = out + (size_t)M_ROWS * CC;         // [B,T,2C]

    float* qkv = nullptr;
    float* yb  = nullptr;
    cudaGetSymbolAddress((void**)&qkv, g_qkv);
    cudaGetSymbolAddress((void**)&yb,  g_y);

    cudaFuncSetAttribute(attn_kernel,
                         cudaFuncAttributeMaxDynamicSharedMemorySize,
                         ATTN_SMEM_BYTES);

    // 1) qkv = x @ W_attn + b_attn       [4096 x 6144]
    {
        dim3 grid(QKV_N / 128, M_ROWS / 128);
        sgemm_bias_kernel<<<grid, 256>>>(x, W_attn, b_attn, qkv,
                                         M_ROWS, QKV_N, CC);
    }
    // 2) cache copy (k,v slice of qkv)
    {
        int n_f4 = M_ROWS * (2 * CC) / 4;             // 4,194,304
        cache_copy_kernel<<<n_f4 / 256, 256>>>(qkv, cache);
    }
    // 3) flash attention -> g_y
    {
        dim3 grid(BB * HH, TT / 64);
        attn_kernel<<<grid, 256, ATTN_SMEM_BYTES>>>(qkv, yb);
    }
    // 4) y = g_y @ W_proj + b_proj -> d_out
    {
        dim3 grid(CC / 128, M_ROWS / 128);
        sgemm_bias_kernel<<<grid, 256>>>(yb, W_proj, b_proj, y_out,
                                         M_ROWS, CC, CC);
    }
}

// round 3
// speedup vs baseline: 1.6946x; 1.6946x over previous
#include <cuda_runtime.h>
#include <cuda_bf16.h>
#include <cstdint>
#include <cstddef>

// Problem constants
#define BB 2
#define TT 2048
#define CC 2048
#define HH 16
#define DH 128
#define M_ROWS (BB*TT)          // 4096
#define QKV_N  (3*CC)           // 6144

// Scratch (allocation-free rule: __device__ globals)
__device__ float g_qkv[(size_t)M_ROWS * QKV_N];   // 96 MB
__device__ float g_y  [(size_t)M_ROWS * CC];      // 32 MB

// ---------------------------------------------------------------------------
// tf32 helpers (plain sm_80+ PTX; no sm_103a-gated instructions)
// ---------------------------------------------------------------------------
__device__ __forceinline__ float f2tf32f(float x) {
    uint32_t o;
    asm("cvt.rna.tf32.f32 %0, %1;" : "=r"(o) : "f"(x));
    return __uint_as_float(o);
}

__device__ __forceinline__ void mma16n8k8(float* c, const float* a, const float* b) {
    const uint32_t* A = reinterpret_cast<const uint32_t*>(a);
    const uint32_t* B = reinterpret_cast<const uint32_t*>(b);
    asm volatile(
        "mma.sync.aligned.m16n8k8.row.col.f32.tf32.tf32.f32 "
        "{%0,%1,%2,%3}, {%4,%5,%6,%7}, {%8,%9}, {%0,%1,%2,%3};"
        : "+f"(c[0]), "+f"(c[1]), "+f"(c[2]), "+f"(c[3])
        : "r"(A[0]), "r"(A[1]), "r"(A[2]), "r"(A[3]), "r"(B[0]), "r"(B[1]));
}

// ---------------------------------------------------------------------------
// tf32 mma.sync GEMM:  C[M,N] = A[M,K] @ W[K,N] + bias[N]
// BM=BN=128, BK=32. 256 threads = 8 warps (4m x 2n), warp tile 32x64.
// A smem [m][k] pad 36; B smem [k][n] pad 136 (loads from W coalesced).
// Double-buffered with register prefetch.
// ---------------------------------------------------------------------------
#define GBM 128
#define GBN 128
#define GBK 32
#define APAD 36
#define BPAD 136
#define A_TILE (GBM * APAD)            // 4608 floats
#define B_TILE (GBK * BPAD)            // 4352 floats
#define GEMM_SMEM ((2 * A_TILE + 2 * B_TILE) * 4)   // 71680 B

__global__ __launch_bounds__(256)
void tf32_gemm_kernel(const float* __restrict__ A, const float* __restrict__ W,
                      const float* __restrict__ bias, float* __restrict__ C,
                      int M, int N, int K) {
    extern __shared__ float sm[];
    float* As = sm;                     // [2][128*36]
    float* Bs = sm + 2 * A_TILE;        // [2][32*136]

    const int tid  = threadIdx.x;
    const int wid  = tid >> 5;
    const int lane = tid & 31;
    const int g    = lane >> 2;         // 0..7
    const int tg   = lane & 3;          // 0..3
    const int wm   = (wid & 3) * 32;    // warp m offset in tile
    const int wn   = (wid >> 2) * 64;   // warp n offset in tile
    const int m0   = blockIdx.y * GBM;
    const int n0   = blockIdx.x * GBN;

    // Per-thread global load coordinates (constant across chunks)
    int rA[4], cA[4], rB[4], cB[4];
#pragma unroll
    for (int i = 0; i < 4; i++) {
        int ia = i * 256 + tid;
        rA[i] = ia >> 3;  cA[i] = ia & 7;    // A: 128 rows x 8 float4
        rB[i] = ia >> 5;  cB[i] = ia & 31;   // B: 32 rows x 32 float4
    }

    float c[2][8][4];
#pragma unroll
    for (int i = 0; i < 2; i++)
#pragma unroll
        for (int j = 0; j < 8; j++)
#pragma unroll
            for (int q = 0; q < 4; q++) c[i][j][q] = 0.0f;

    const int NC = K / GBK;   // 64
    float4 va[4], vb[4];

    // ---- prologue: load chunk 0 ----
#pragma unroll
    for (int i = 0; i < 4; i++) {
        va[i] = *(const float4*)(A + (size_t)(m0 + rA[i]) * K + cA[i] * 4);
        vb[i] = *(const float4*)(W + (size_t)rB[i] * N + n0 + cB[i] * 4);
    }
#pragma unroll
    for (int i = 0; i < 4; i++) {
        float4 t;
        t.x = f2tf32f(va[i].x); t.y = f2tf32f(va[i].y);
        t.z = f2tf32f(va[i].z); t.w = f2tf32f(va[i].w);
        *(float4*)&As[rA[i] * APAD + cA[i] * 4] = t;
        t.x = f2tf32f(vb[i].x); t.y = f2tf32f(vb[i].y);
        t.z = f2tf32f(vb[i].z); t.w = f2tf32f(vb[i].w);
        *(float4*)&Bs[rB[i] * BPAD + cB[i] * 4] = t;
    }
    __syncthreads();

    for (int ch = 0; ch < NC; ++ch) {
        const int buf = ch & 1;
        const float* Ab = As + buf * A_TILE;
        const float* Bb = Bs + buf * B_TILE;

        // prefetch next chunk into registers
        if (ch + 1 < NC) {
            int k0n = (ch + 1) * GBK;
#pragma unroll
            for (int i = 0; i < 4; i++) {
                va[i] = *(const float4*)(A + (size_t)(m0 + rA[i]) * K + k0n + cA[i] * 4);
                vb[i] = *(const float4*)(W + (size_t)(k0n + rB[i]) * N + n0 + cB[i] * 4);
            }
        }

        // compute on current buffer
#pragma unroll
        for (int s = 0; s < 4; s++) {
            const int ks = s * 8;
            float af[2][4];
#pragma unroll
            for (int i = 0; i < 2; i++) {
                int r0 = wm + 16 * i + g;
                af[i][0] = Ab[(r0)     * APAD + ks + tg];
                af[i][1] = Ab[(r0 + 8) * APAD + ks + tg];
                af[i][2] = Ab[(r0)     * APAD + ks + tg + 4];
                af[i][3] = Ab[(r0 + 8) * APAD + ks + tg + 4];
            }
            float bf[8][2];
#pragma unroll
            for (int j = 0; j < 8; j++) {
                int cn = wn + 8 * j + g;
                bf[j][0] = Bb[(ks + tg)     * BPAD + cn];
                bf[j][1] = Bb[(ks + tg + 4) * BPAD + cn];
            }
#pragma unroll
            for (int i = 0; i < 2; i++)
#pragma unroll
                for (int j = 0; j < 8; j++)
                    mma16n8k8(c[i][j], af[i], bf[j]);
        }
        __syncthreads();

        // store prefetched regs into other buffer
        if (ch + 1 < NC) {
            float* An = As + (buf ^ 1) * A_TILE;
            float* Bn = Bs + (buf ^ 1) * B_TILE;
#pragma unroll
            for (int i = 0; i < 4; i++) {
                float4 t;
                t.x = f2tf32f(va[i].x); t.y = f2tf32f(va[i].y);
                t.z = f2tf32f(va[i].z); t.w = f2tf32f(va[i].w);
                *(float4*)&An[rA[i] * APAD + cA[i] * 4] = t;
                t.x = f2tf32f(vb[i].x); t.y = f2tf32f(vb[i].y);
                t.z = f2tf32f(vb[i].z); t.w = f2tf32f(vb[i].w);
                *(float4*)&Bn[rB[i] * BPAD + cB[i] * 4] = t;
            }
            __syncthreads();
        }
    }

    // ---- epilogue: bias add, direct stores ----
#pragma unroll
    for (int i = 0; i < 2; i++) {
        int row = m0 + wm + 16 * i + g;
#pragma unroll
        for (int j = 0; j < 8; j++) {
            int col = n0 + wn + 8 * j + 2 * tg;
            float2 bv = *(const float2*)(bias + col);
            float2 o0, o1;
            o0.x = c[i][j][0] + bv.x;  o0.y = c[i][j][1] + bv.y;
            o1.x = c[i][j][2] + bv.x;  o1.y = c[i][j][3] + bv.y;
            *(float2*)(C + (size_t)row * N + col) = o0;
            *(float2*)(C + (size_t)(row + 8) * N + col) = o1;
        }
    }
}

// ---------------------------------------------------------------------------
// Flash attention (fp32, causal) — unchanged.
// ---------------------------------------------------------------------------
#define ATTN_SMEM_FLOATS (64*128 + 128*68 + 64*128 + 64*68)
#define ATTN_SMEM_BYTES  (ATTN_SMEM_FLOATS * 4)

__global__ __launch_bounds__(256)
void attn_kernel(const float* __restrict__ qkv, float* __restrict__ y) {
    extern __shared__ float sm[];
    float* Qs = sm;
    float* Kt = Qs + 64 * 128;
    float* Vs = Kt + 128 * 68;
    float* Ps = Vs + 64 * 128;

    const int tid = threadIdx.x;
    const int tx = tid & 15;
    const int ty = tid >> 4;
    const int bh = blockIdx.x;
    const int qt = blockIdx.y;
    const int b = bh >> 4;
    const int h = bh & 15;
    const int q0 = qt * 64;

    const float SCALE = 0.08838834764831845f;
    const size_t RS = (size_t)QKV_N;

    const float* qbase = qkv + (size_t)b * TT * RS + (size_t)h * DH;
    const float* kbase = qbase + CC;
    const float* vbase = qbase + 2 * CC;

    for (int i = tid; i < 64 * 32; i += 256) {
        int r = i >> 5, dv = i & 31;
        *(float4*)&Qs[r * 128 + dv * 4] =
            *(const float4*)(qbase + (size_t)(q0 + r) * RS + dv * 4);
    }

    float m_prev[4], l_acc[4], acc[4][8];
#pragma unroll
    for (int i = 0; i < 4; i++) {
        m_prev[i] = -1e30f;
        l_acc[i] = 0.0f;
#pragma unroll
        for (int j = 0; j < 8; j++) acc[i][j] = 0.0f;
    }

    const int ntiles = qt + 1;
    for (int kt = 0; kt < ntiles; ++kt) {
        const int k0 = kt * 64;
        __syncthreads();

        for (int i = tid; i < 64 * 32; i += 256) {
            int r = i >> 5, dv = i & 31;
            float4 kv = *(const float4*)(kbase + (size_t)(k0 + r) * RS + dv * 4);
            int dbase = dv * 4;
            Kt[(dbase + 0) * 68 + r] = kv.x;
            Kt[(dbase + 1) * 68 + r] = kv.y;
            Kt[(dbase + 2) * 68 + r] = kv.z;
            Kt[(dbase + 3) * 68 + r] = kv.w;
            *(float4*)&Vs[r * 128 + dbase] =
                *(const float4*)(vbase + (size_t)(k0 + r) * RS + dbase);
        }
        __syncthreads();

        float s[4][4];
#pragma unroll
        for (int i = 0; i < 4; i++)
#pragma unroll
            for (int j = 0; j < 4; j++) s[i][j] = 0.0f;

        for (int d = 0; d < 128; d += 4) {
            float4 a0 = *(float4*)&Qs[(ty * 4 + 0) * 128 + d];
            float4 a1 = *(float4*)&Qs[(ty * 4 + 1) * 128 + d];
            float4 a2 = *(float4*)&Qs[(ty * 4 + 2) * 128 + d];
            float4 a3 = *(float4*)&Qs[(ty * 4 + 3) * 128 + d];
            float4 b0 = *(float4*)&Kt[(d + 0) * 68 + tx * 4];
            float4 b1 = *(float4*)&Kt[(d + 1) * 68 + tx * 4];
            float4 b2 = *(float4*)&Kt[(d + 2) * 68 + tx * 4];
            float4 b3 = *(float4*)&Kt[(d + 3) * 68 + tx * 4];
#define SROW(i, av)                                             \
            s[i][0] = fmaf(av.x, b0.x, s[i][0]);                \
            s[i][1] = fmaf(av.x, b0.y, s[i][1]);                \
            s[i][2] = fmaf(av.x, b0.z, s[i][2]);                \
            s[i][3] = fmaf(av.x, b0.w, s[i][3]);                \
            s[i][0] = fmaf(av.y, b1.x, s[i][0]);                \
            s[i][1] = fmaf(av.y, b1.y, s[i][1]);                \
            s[i][2] = fmaf(av.y, b1.z, s[i][2]);                \
            s[i][3] = fmaf(av.y, b1.w, s[i][3]);                \
            s[i][0] = fmaf(av.z, b2.x, s[i][0]);                \
            s[i][1] = fmaf(av.z, b2.y, s[i][1]);                \
            s[i][2] = fmaf(av.z, b2.z, s[i][2]);                \
            s[i][3] = fmaf(av.z, b2.w, s[i][3]);                \
            s[i][0] = fmaf(av.w, b3.x, s[i][0]);                \
            s[i][1] = fmaf(av.w, b3.y, s[i][1]);                \
            s[i][2] = fmaf(av.w, b3.z, s[i][2]);                \
            s[i][3] = fmaf(av.w, b3.w, s[i][3]);
            SROW(0, a0) SROW(1, a1) SROW(2, a2) SROW(3, a3)
#undef SROW
        }

        float mt[4];
#pragma unroll
        for (int i = 0; i < 4; i++) {
            int gr = q0 + ty * 4 + i;
            float mx = -1e30f;
#pragma unroll
            for (int j = 0; j < 4; j++) {
                int gc = k0 + tx * 4 + j;
                float sv = s[i][j] * SCALE;
                sv = (gc > gr) ? -1e30f : sv;
                s[i][j] = sv;
                mx = fmaxf(mx, sv);
            }
            mt[i] = mx;
        }
#pragma unroll
        for (int off = 8; off >= 1; off >>= 1) {
#pragma unroll
            for (int i = 0; i < 4; i++)
                mt[i] = fmaxf(mt[i], __shfl_xor_sync(0xffffffffu, mt[i], off));
        }

#pragma unroll
        for (int i = 0; i < 4; i++) {
            float mn = fmaxf(m_prev[i], mt[i]);
            float sc = __expf(m_prev[i] - mn);
            float ls = 0.0f;
#pragma unroll
            for (int j = 0; j < 4; j++) {
                float p = __expf(s[i][j] - mn);
                s[i][j] = p;
                ls += p;
            }
#pragma unroll
            for (int off = 8; off >= 1; off >>= 1)
                ls += __shfl_xor_sync(0xffffffffu, ls, off);
            l_acc[i] = l_acc[i] * sc + ls;
            m_prev[i] = mn;
#pragma unroll
            for (int j = 0; j < 8; j++) acc[i][j] *= sc;
            float4 pv = make_float4(s[i][0], s[i][1], s[i][2], s[i][3]);
            *(float4*)&Ps[(ty * 4 + i) * 68 + tx * 4] = pv;
        }
        __syncwarp();

        for (int k = 0; k < 64; ++k) {
            float4 v0 = *(float4*)&Vs[k * 128 + tx * 8];
            float4 v1 = *(float4*)&Vs[k * 128 + tx * 8 + 4];
#pragma unroll
            for (int i = 0; i < 4; i++) {
                float p = Ps[(ty * 4 + i) * 68 + k];
                acc[i][0] = fmaf(p, v0.x, acc[i][0]);
                acc[i][1] = fmaf(p, v0.y, acc[i][1]);
                acc[i][2] = fmaf(p, v0.z, acc[i][2]);
                acc[i][3] = fmaf(p, v0.w, acc[i][3]);
                acc[i][4] = fmaf(p, v1.x, acc[i][4]);
                acc[i][5] = fmaf(p, v1.y, acc[i][5]);
                acc[i][6] = fmaf(p, v1.z, acc[i][6]);
                acc[i][7] = fmaf(p, v1.w, acc[i][7]);
            }
        }
        __syncwarp();
    }

#pragma unroll
    for (int i = 0; i < 4; i++) {
        float inv = 1.0f / l_acc[i];
        size_t orow = (size_t)(b * TT + q0 + ty * 4 + i) * CC + h * DH + tx * 8;
        float4 o0, o1;
        o0.x = acc[i][0] * inv; o0.y = acc[i][1] * inv;
        o0.z = acc[i][2] * inv; o0.w = acc[i][3] * inv;
        o1.x = acc[i][4] * inv; o1.y = acc[i][5] * inv;
        o1.z = acc[i][6] * inv; o1.w = acc[i][7] * inv;
        *(float4*)(y + orow) = o0;
        *(float4*)(y + orow + 4) = o1;
    }
}

// ---------------------------------------------------------------------------
// cache[bt, 0:2C] = qkv[bt, C:3C]
// ---------------------------------------------------------------------------
__global__ __launch_bounds__(256)
void cache_copy_kernel(const float* __restrict__ qkv, float* __restrict__ cache) {
    int idx = blockIdx.x * blockDim.x + threadIdx.x;
    int bt = idx >> 10;
    int c4 = idx & 1023;
    const float4* src = (const float4*)qkv + (size_t)bt * 1536 + 512 + c4;
    ((float4*)cache)[idx] = *src;
}

// ---------------------------------------------------------------------------
extern "C" void kernel_launch(void* const* d_in, const int* in_sizes, int n_in,
                              void* d_out, int out_size) {
    (void)in_sizes; (void)n_in; (void)out_size;
    const float* x      = (const float*)d_in[0];
    const float* W_attn = (const float*)d_in[2];
    const float* b_attn = (const float*)d_in[3];
    const float* W_proj = (const float*)d_in[4];
    const float* b_proj = (const float*)d_in[5];

    float* out   = (float*)d_out;
    float* y_out = out;
    float* cache = out + (size_t)M_ROWS * CC;

    float *qkv = nullptr, *yb = nullptr;
    cudaGetSymbolAddress((void**)&qkv, g_qkv);
    cudaGetSymbolAddress((void**)&yb,  g_y);

    cudaFuncSetAttribute(attn_kernel,
                         cudaFuncAttributeMaxDynamicSharedMemorySize,
                         ATTN_SMEM_BYTES);
    cudaFuncSetAttribute(tf32_gemm_kernel,
                         cudaFuncAttributeMaxDynamicSharedMemorySize,
                         GEMM_SMEM);

    // 1) qkv = x @ W_attn + b_attn   [4096 x 6144], K=2048
    {
        dim3 grid(QKV_N / GBN, M_ROWS / GBM);   // (48, 32)
        tf32_gemm_kernel<<<grid, 256, GEMM_SMEM>>>(x, W_attn, b_attn, qkv,
                                                   M_ROWS, QKV_N, CC);
    }
    // 2) cache copy
    {
        int n_f4 = M_ROWS * (2 * CC) / 4;
        cache_copy_kernel<<<n_f4 / 256, 256>>>(qkv, cache);
    }
    // 3) flash attention
    {
        dim3 grid(BB * HH, TT / 64);
        attn_kernel<<<grid, 256, ATTN_SMEM_BYTES>>>(qkv, yb);
    }
    // 4) y = attn_out @ W_proj + b_proj
    {
        dim3 grid(CC / GBN, M_ROWS / GBM);      // (16, 32)
        tf32_gemm_kernel<<<grid, 256, GEMM_SMEM>>>(yb, W_proj, b_proj, y_out,
                                                   M_ROWS, CC, CC);
    }
}

// round 4
// speedup vs baseline: 2.8238x; 1.6664x over previous
#include <cuda_runtime.h>
#include <cuda_bf16.h>
#include <cstdint>
#include <cstddef>

// Problem constants
#define BB 2
#define TT 2048
#define CC 2048
#define HH 16
#define DH 128
#define M_ROWS (BB*TT)          // 4096
#define QKV_N  (3*CC)           // 6144

// Scratch (allocation-free rule: __device__ globals)
__device__ float g_qkv[(size_t)M_ROWS * QKV_N];   // 96 MB
__device__ float g_y  [(size_t)M_ROWS * CC];      // 32 MB

// ---------------------------------------------------------------------------
// tf32 helpers (plain sm_80+ PTX; no sm_103a-gated instructions)
// ---------------------------------------------------------------------------
__device__ __forceinline__ float f2tf32f(float x) {
    uint32_t o;
    asm("cvt.rna.tf32.f32 %0, %1;" : "=r"(o) : "f"(x));
    return __uint_as_float(o);
}

__device__ __forceinline__ void mma16n8k8(float* c, const float* a, const float* b) {
    const uint32_t* A = reinterpret_cast<const uint32_t*>(a);
    const uint32_t* B = reinterpret_cast<const uint32_t*>(b);
    asm volatile(
        "mma.sync.aligned.m16n8k8.row.col.f32.tf32.tf32.f32 "
        "{%0,%1,%2,%3}, {%4,%5,%6,%7}, {%8,%9}, {%0,%1,%2,%3};"
        : "+f"(c[0]), "+f"(c[1]), "+f"(c[2]), "+f"(c[3])
        : "r"(A[0]), "r"(A[1]), "r"(A[2]), "r"(A[3]), "r"(B[0]), "r"(B[1]));
}

// ---------------------------------------------------------------------------
// tf32 mma.sync GEMM:  C[M,N] = A[M,K] @ W[K,N] + bias[N]
// BM=BN=128, BK=32. 256 threads = 8 warps (4m x 2n), warp tile 32x64.
// Optional fused cache store: for col >= CC, also write C value to
// cache[row][col-CC]  (cache row stride 2*CC).
// ---------------------------------------------------------------------------
#define GBM 128
#define GBN 128
#define GBK 32
#define APAD 36
#define BPAD 136
#define A_TILE (GBM * APAD)            // 4608 floats
#define B_TILE (GBK * BPAD)            // 4352 floats
#define GEMM_SMEM ((2 * A_TILE + 2 * B_TILE) * 4)   // 71680 B

__global__ __launch_bounds__(256)
void tf32_gemm_kernel(const float* __restrict__ A, const float* __restrict__ W,
                      const float* __restrict__ bias, float* __restrict__ C,
                      float* __restrict__ cache,
                      int M, int N, int K) {
    extern __shared__ float sm[];
    float* As = sm;                     // [2][128*36]
    float* Bs = sm + 2 * A_TILE;        // [2][32*136]

    const int tid  = threadIdx.x;
    const int wid  = tid >> 5;
    const int lane = tid & 31;
    const int g    = lane >> 2;         // 0..7
    const int tg   = lane & 3;          // 0..3
    const int wm   = (wid & 3) * 32;    // warp m offset in tile
    const int wn   = (wid >> 2) * 64;   // warp n offset in tile
    const int m0   = blockIdx.y * GBM;
    const int n0   = blockIdx.x * GBN;

    int rA[4], cA[4], rB[4], cB[4];
#pragma unroll
    for (int i = 0; i < 4; i++) {
        int ia = i * 256 + tid;
        rA[i] = ia >> 3;  cA[i] = ia & 7;    // A: 128 rows x 8 float4
        rB[i] = ia >> 5;  cB[i] = ia & 31;   // B: 32 rows x 32 float4
    }

    float c[2][8][4];
#pragma unroll
    for (int i = 0; i < 2; i++)
#pragma unroll
        for (int j = 0; j < 8; j++)
#pragma unroll
            for (int q = 0; q < 4; q++) c[i][j][q] = 0.0f;

    const int NC = K / GBK;   // 64
    float4 va[4], vb[4];

#pragma unroll
    for (int i = 0; i < 4; i++) {
        va[i] = *(const float4*)(A + (size_t)(m0 + rA[i]) * K + cA[i] * 4);
        vb[i] = *(const float4*)(W + (size_t)rB[i] * N + n0 + cB[i] * 4);
    }
#pragma unroll
    for (int i = 0; i < 4; i++) {
        float4 t;
        t.x = f2tf32f(va[i].x); t.y = f2tf32f(va[i].y);
        t.z = f2tf32f(va[i].z); t.w = f2tf32f(va[i].w);
        *(float4*)&As[rA[i] * APAD + cA[i] * 4] = t;
        t.x = f2tf32f(vb[i].x); t.y = f2tf32f(vb[i].y);
        t.z = f2tf32f(vb[i].z); t.w = f2tf32f(vb[i].w);
        *(float4*)&Bs[rB[i] * BPAD + cB[i] * 4] = t;
    }
    __syncthreads();

    for (int ch = 0; ch < NC; ++ch) {
        const int buf = ch & 1;
        const float* Ab = As + buf * A_TILE;
        const float* Bb = Bs + buf * B_TILE;

        if (ch + 1 < NC) {
            int k0n = (ch + 1) * GBK;
#pragma unroll
            for (int i = 0; i < 4; i++) {
                va[i] = *(const float4*)(A + (size_t)(m0 + rA[i]) * K + k0n + cA[i] * 4);
                vb[i] = *(const float4*)(W + (size_t)(k0n + rB[i]) * N + n0 + cB[i] * 4);
            }
        }

#pragma unroll
        for (int s = 0; s < 4; s++) {
            const int ks = s * 8;
            float af[2][4];
#pragma unroll
            for (int i = 0; i < 2; i++) {
                int r0 = wm + 16 * i + g;
                af[i][0] = Ab[(r0)     * APAD + ks + tg];
                af[i][1] = Ab[(r0 + 8) * APAD + ks + tg];
                af[i][2] = Ab[(r0)     * APAD + ks + tg + 4];
                af[i][3] = Ab[(r0 + 8) * APAD + ks + tg + 4];
            }
            float bf[8][2];
#pragma unroll
            for (int j = 0; j < 8; j++) {
                int cn = wn + 8 * j + g;
                bf[j][0] = Bb[(ks + tg)     * BPAD + cn];
                bf[j][1] = Bb[(ks + tg + 4) * BPAD + cn];
            }
#pragma unroll
            for (int i = 0; i < 2; i++)
#pragma unroll
                for (int j = 0; j < 8; j++)
                    mma16n8k8(c[i][j], af[i], bf[j]);
        }
        __syncthreads();

        if (ch + 1 < NC) {
            float* An = As + (buf ^ 1) * A_TILE;
            float* Bn = Bs + (buf ^ 1) * B_TILE;
#pragma unroll
            for (int i = 0; i < 4; i++) {
                float4 t;
                t.x = f2tf32f(va[i].x); t.y = f2tf32f(va[i].y);
                t.z = f2tf32f(va[i].z); t.w = f2tf32f(va[i].w);
                *(float4*)&An[rA[i] * APAD + cA[i] * 4] = t;
                t.x = f2tf32f(vb[i].x); t.y = f2tf32f(vb[i].y);
                t.z = f2tf32f(vb[i].z); t.w = f2tf32f(vb[i].w);
                *(float4*)&Bn[rB[i] * BPAD + cB[i] * 4] = t;
            }
            __syncthreads();
        }
    }

    // ---- epilogue: bias add, direct stores (+ optional fused cache store) ----
#pragma unroll
    for (int i = 0; i < 2; i++) {
        int row = m0 + wm + 16 * i + g;
#pragma unroll
        for (int j = 0; j < 8; j++) {
            int col = n0 + wn + 8 * j + 2 * tg;
            float2 bv = *(const float2*)(bias + col);
            float2 o0, o1;
            o0.x = c[i][j][0] + bv.x;  o0.y = c[i][j][1] + bv.y;
            o1.x = c[i][j][2] + bv.x;  o1.y = c[i][j][3] + bv.y;
            *(float2*)(C + (size_t)row * N + col) = o0;
            *(float2*)(C + (size_t)(row + 8) * N + col) = o1;
            if (cache != nullptr && col >= CC) {
                int cc = col - CC;
                *(float2*)(cache + (size_t)row * (2 * CC) + cc) = o0;
                *(float2*)(cache + (size_t)(row + 8) * (2 * CC) + cc) = o1;
            }
        }
    }
}

// ---------------------------------------------------------------------------
// Flash attention with tf32 mma.sync (causal).
// Grid: (B*H, T/128). 256 threads = 8 warps; warp w owns q-rows [16w,16w+16)
// of a 128-row Q tile and ALL 64 kv cols (row softmax stays in-quad).
// smem: Q[128][132], K[64][132], V[64][132], P[128][68]  (~166 KB)
// ---------------------------------------------------------------------------
#define AQP 132
#define AKP 132
#define APP 68
#define ATTN_SMEM_FLOATS (128*AQP + 64*AKP + 64*AKP + 128*APP)
#define ATTN_SMEM_BYTES  (ATTN_SMEM_FLOATS * 4)

__global__ __launch_bounds__(256)
void attn_mma_kernel(const float* __restrict__ qkv, float* __restrict__ y) {
    extern __shared__ float sm[];
    float* Qs = sm;                       // [128][132]
    float* Ks = Qs + 128 * AQP;           // [64][132]
    float* Vs = Ks + 64 * AKP;            // [64][132]
    float* Ps = Vs + 64 * AKP;            // [128][68]

    const int tid  = threadIdx.x;
    const int wid  = tid >> 5;
    const int lane = tid & 31;
    const int g    = lane >> 2;           // 0..7
    const int tg   = lane & 3;            // 0..3
    const int bh   = blockIdx.x;
    const int b    = bh >> 4;
    const int h    = bh & 15;
    const int qt   = gridDim.y - 1 - blockIdx.y;   // heavy tiles first
    const int q0   = qt * 128;
    const int wr0  = wid * 16;            // warp's row offset within tile

    const float SCALE = 0.08838834764831845f;      // 1/sqrt(128)
    const size_t RS = (size_t)QKV_N;

    const float* qbase = qkv + (size_t)b * TT * RS + (size_t)h * DH;
    const float* kbase = qbase + CC;
    const float* vbase = qbase + 2 * CC;

    // Load + round Q tile (128 x 128)
    for (int i = tid; i < 128 * 32; i += 256) {
        int r = i >> 5, dv = i & 31;
        float4 v = *(const float4*)(qbase + (size_t)(q0 + r) * RS + dv * 4);
        float4 t;
        t.x = f2tf32f(v.x); t.y = f2tf32f(v.y);
        t.z = f2tf32f(v.z); t.w = f2tf32f(v.w);
        *(float4*)&Qs[r * AQP + dv * 4] = t;
    }

    float m_prev[2] = {-1e30f, -1e30f};
    float l_acc[2]  = {0.0f, 0.0f};
    float acc[16][4];
#pragma unroll
    for (int nj = 0; nj < 16; nj++)
#pragma unroll
        for (int q = 0; q < 4; q++) acc[nj][q] = 0.0f;

    const int ntiles = 2 * qt + 2;   // KV tiles of 64 up to row q0+127

    for (int kt = 0; kt < ntiles; ++kt) {
        const int k0 = kt * 64;
        __syncthreads();   // prior-iter K/V reads complete

        // Load + round K, V tiles (64 x 128 each)
        for (int i = tid; i < 64 * 32; i += 256) {
            int r = i >> 5, dv = i & 31;
            float4 kv = *(const float4*)(kbase + (size_t)(k0 + r) * RS + dv * 4);
            float4 vv = *(const float4*)(vbase + (size_t)(k0 + r) * RS + dv * 4);
            float4 t;
            t.x = f2tf32f(kv.x); t.y = f2tf32f(kv.y);
            t.z = f2tf32f(kv.z); t.w = f2tf32f(kv.w);
            *(float4*)&Ks[r * AKP + dv * 4] = t;
            t.x = f2tf32f(vv.x); t.y = f2tf32f(vv.y);
            t.z = f2tf32f(vv.z); t.w = f2tf32f(vv.w);
            *(float4*)&Vs[r * AKP + dv * 4] = t;
        }
        __syncthreads();

        // ---- S = Q K^T : warp computes 16 x 64, frags cs[8][4] ----
        float cs[8][4];
#pragma unroll
        for (int j = 0; j < 8; j++)
#pragma unroll
            for (int q = 0; q < 4; q++) cs[j][q] = 0.0f;

#pragma unroll
        for (int ks = 0; ks < 128; ks += 8) {
            float a[4];
            a[0] = Qs[(wr0 + g)     * AQP + ks + tg];
            a[1] = Qs[(wr0 + g + 8) * AQP + ks + tg];
            a[2] = Qs[(wr0 + g)     * AQP + ks + tg + 4];
            a[3] = Qs[(wr0 + g + 8) * AQP + ks + tg + 4];
#pragma unroll
            for (int j = 0; j < 8; j++) {
                float bb[2];
                bb[0] = Ks[(8 * j + g) * AKP + ks + tg];
                bb[1] = Ks[(8 * j + g) * AKP + ks + tg + 4];
                mma16n8k8(cs[j], a, bb);
            }
        }

        // ---- scale + causal mask + row max ----
        const int gr0 = q0 + wr0 + g;
        const int gr1 = gr0 + 8;
        float mx0 = -1e30f, mx1 = -1e30f;
#pragma unroll
        for (int j = 0; j < 8; j++) {
            int gc0 = k0 + 8 * j + 2 * tg;
            int gc1 = gc0 + 1;
            float s0 = cs[j][0] * SCALE; if (gc0 > gr0) s0 = -1e30f;
            float s1 = cs[j][1] * SCALE; if (gc1 > gr0) s1 = -1e30f;
            float s2 = cs[j][2] * SCALE; if (gc0 > gr1) s2 = -1e30f;
            float s3 = cs[j][3] * SCALE; if (gc1 > gr1) s3 = -1e30f;
            cs[j][0] = s0; cs[j][1] = s1; cs[j][2] = s2; cs[j][3] = s3;
            mx0 = fmaxf(mx0, fmaxf(s0, s1));
            mx1 = fmaxf(mx1, fmaxf(s2, s3));
        }
        mx0 = fmaxf(mx0, __shfl_xor_sync(0xffffffffu, mx0, 1));
        mx0 = fmaxf(mx0, __shfl_xor_sync(0xffffffffu, mx0, 2));
        mx1 = fmaxf(mx1, __shfl_xor_sync(0xffffffffu, mx1, 1));
        mx1 = fmaxf(mx1, __shfl_xor_sync(0xffffffffu, mx1, 2));

        float mn0 = fmaxf(m_prev[0], mx0);
        float mn1 = fmaxf(m_prev[1], mx1);
        float f0 = __expf(m_prev[0] - mn0);
        float f1 = __expf(m_prev[1] - mn1);
        m_prev[0] = mn0; m_prev[1] = mn1;

        float ls0 = 0.0f, ls1 = 0.0f;
#pragma unroll
        for (int j = 0; j < 8; j++) {
            float p0 = __expf(cs[j][0] - mn0);
            float p1 = __expf(cs[j][1] - mn0);
            float p2 = __expf(cs[j][2] - mn1);
            float p3 = __expf(cs[j][3] - mn1);
            ls0 += p0 + p1;
            ls1 += p2 + p3;
            float2 w0 = make_float2(f2tf32f(p0), f2tf32f(p1));
            float2 w1 = make_float2(f2tf32f(p2), f2tf32f(p3));
            *(float2*)&Ps[(wr0 + g)     * APP + 8 * j + 2 * tg] = w0;
            *(float2*)&Ps[(wr0 + g + 8) * APP + 8 * j + 2 * tg] = w1;
        }
        ls0 += __shfl_xor_sync(0xffffffffu, ls0, 1);
        ls0 += __shfl_xor_sync(0xffffffffu, ls0, 2);
        ls1 += __shfl_xor_sync(0xffffffffu, ls1, 1);
        ls1 += __shfl_xor_sync(0xffffffffu, ls1, 2);
        l_acc[0] = l_acc[0] * f0 + ls0;
        l_acc[1] = l_acc[1] * f1 + ls1;

#pragma unroll
        for (int nj = 0; nj < 16; nj++) {
            acc[nj][0] *= f0; acc[nj][1] *= f0;
            acc[nj][2] *= f1; acc[nj][3] *= f1;
        }
        __syncwarp();   // P visible within warp

        // ---- acc += P @ V : warp 16 x 128, frags acc[16][4] ----
#pragma unroll
        for (int ks = 0; ks < 64; ks += 8) {
            float a[4];
            a[0] = Ps[(wr0 + g)     * APP + ks + tg];
            a[1] = Ps[(wr0 + g + 8) * APP + ks + tg];
            a[2] = Ps[(wr0 + g)     * APP + ks + tg + 4];
            a[3] = Ps[(wr0 + g + 8) * APP + ks + tg + 4];
#pragma unroll
            for (int nj = 0; nj < 16; nj++) {
                float bb[2];
                bb[0] = Vs[(ks + tg)     * AKP + 8 * nj + g];
                bb[1] = Vs[(ks + tg + 4) * AKP + 8 * nj + g];
                mma16n8k8(acc[nj], a, bb);
            }
        }
        __syncwarp();   // P reads done before next-iter overwrite
    }

    // ---- normalize + write y[b, q, h*128 + d] ----
    float inv0 = 1.0f / l_acc[0];
    float inv1 = 1.0f / l_acc[1];
    size_t row0 = (size_t)(b * TT + q0 + wr0 + g);
    size_t row1 = row0 + 8;
#pragma unroll
    for (int nj = 0; nj < 16; nj++) {
        int col = h * DH + 8 * nj + 2 * tg;
        float2 o0 = make_float2(acc[nj][0] * inv0, acc[nj][1] * inv0);
        float2 o1 = make_float2(acc[nj][2] * inv1, acc[nj][3] * inv1);
        *(float2*)(y + row0 * CC + col) = o0;
        *(float2*)(y + row1 * CC + col) = o1;
    }
}

// ---------------------------------------------------------------------------
extern "C" void kernel_launch(void* const* d_in, const int* in_sizes, int n_in,
                              void* d_out, int out_size) {
    (void)in_sizes; (void)n_in; (void)out_size;
    const float* x      = (const float*)d_in[0];
    const float* W_attn = (const float*)d_in[2];
    const float* b_attn = (const float*)d_in[3];
    const float* W_proj = (const float*)d_in[4];
    const float* b_proj = (const float*)d_in[5];

    float* out   = (float*)d_out;
    float* y_out = out;
    float* cache = out + (size_t)M_ROWS * CC;

    float *qkv = nullptr, *yb = nullptr;
    cudaGetSymbolAddress((void**)&qkv, g_qkv);
    cudaGetSymbolAddress((void**)&yb,  g_y);

    cudaFuncSetAttribute(attn_mma_kernel,
                         cudaFuncAttributeMaxDynamicSharedMemorySize,
                         ATTN_SMEM_BYTES);
    cudaFuncSetAttribute(tf32_gemm_kernel,
                         cudaFuncAttributeMaxDynamicSharedMemorySize,
                         GEMM_SMEM);

    // 1) qkv = x @ W_attn + b_attn  (fused cache store for cols >= 2048)
    {
        dim3 grid(QKV_N / GBN, M_ROWS / GBM);   // (48, 32)
        tf32_gemm_kernel<<<grid, 256, GEMM_SMEM>>>(x, W_attn, b_attn, qkv,
                                                   cache, M_ROWS, QKV_N, CC);
    }
    // 2) flash attention (tf32 mma)
    {
        dim3 grid(BB * HH, TT / 128);           // (32, 16)
        attn_mma_kernel<<<grid, 256, ATTN_SMEM_BYTES>>>(qkv, yb);
    }
    // 3) y = attn_out @ W_proj + b_proj
    {
        dim3 grid(CC / GBN, M_ROWS / GBM);      // (16, 32)
        tf32_gemm_kernel<<<grid, 256, GEMM_SMEM>>>(yb, W_proj, b_proj, y_out,
                                                   nullptr, M_ROWS, CC, CC);
    }
}